// round 11
// baseline (speedup 1.0000x reference)
#include <cuda_runtime.h>
#include <cuda_fp16.h>

#define DIM   128
#define NC    4
#define N_RNA_MAX  20000
#define N_PROT_MAX 5000
#define EDGES_PER_WARP_ITER 8
#define TARGET_ITERS 2

// Folded weights: M[j][d] = sum_c Wc[c][j] * w_rel[c][d]
__device__ float g_M[NC * DIM];
// fp16 copies of the gather tables: halves the L2 gather flow vs fp32.
__device__ __half g_rna [N_RNA_MAX  * DIM];
__device__ __half g_prot[N_PROT_MAX * DIM];

// Prologue: fold weights (first 512 threads) + convert tables to fp16.
__global__ __launch_bounds__(256) void prep_kernel(
    const float* __restrict__ rna, const float* __restrict__ prot,
    const float* __restrict__ w_rel, const float* __restrict__ w_cls,
    long long nRelem, long long nPelem)
{
    const long long i = (long long)blockIdx.x * blockDim.x + threadIdx.x;

    if (i < NC * DIM) {
        int j = (int)i / DIM, d = (int)i % DIM;
        float s = 0.f;
#pragma unroll
        for (int c = 0; c < NC; ++c)
            s += w_cls[c * NC + j] * w_rel[c * DIM + d];
        g_M[j * DIM + d] = s;
    }

    const long long base = i * 8;
    if (base >= nRelem + nPelem) return;
    const float* src;  __half* dst;  long long off;
    if (base < nRelem) { src = rna;  dst = g_rna;  off = base; }
    else               { src = prot; dst = g_prot; off = base - nRelem; }

    float4 f0 = *reinterpret_cast<const float4*>(src + off);
    float4 f1 = *reinterpret_cast<const float4*>(src + off + 4);
    __half2 h0 = __floats2half2_rn(f0.x, f0.y);
    __half2 h1 = __floats2half2_rn(f0.z, f0.w);
    __half2 h2 = __floats2half2_rn(f1.x, f1.y);
    __half2 h3 = __floats2half2_rn(f1.z, f1.w);
    uint4 o;
    o.x = *reinterpret_cast<unsigned*>(&h0);
    o.y = *reinterpret_cast<unsigned*>(&h1);
    o.z = *reinterpret_cast<unsigned*>(&h2);
    o.w = *reinterpret_cast<unsigned*>(&h3);
    *reinterpret_cast<uint4*>(dst + off) = o;
}

// Streaming 16B load (guaranteed-miss gathers: skip L1 allocate).
__device__ __forceinline__ uint4 ldg_na(const uint4* p) {
    uint4 v;
    asm("ld.global.L1::no_allocate.v4.u32 {%0,%1,%2,%3}, [%4];"
        : "=r"(v.x), "=r"(v.y), "=r"(v.z), "=r"(v.w) : "l"(p));
    return v;
}

// ---- packed f32x2 helpers (Blackwell FFMA2: PTX-only, plain compute_103) ----
__device__ __forceinline__ unsigned long long pack2(float x, float y) {
    unsigned long long r;
    asm("mov.b64 %0, {%1, %2};" : "=l"(r) : "f"(x), "f"(y));
    return r;
}
__device__ __forceinline__ unsigned long long fma2(
    unsigned long long a, unsigned long long b, unsigned long long c) {
    unsigned long long d;
    asm("fma.rn.f32x2 %0, %1, %2, %3;" : "=l"(d) : "l"(a), "l"(b), "l"(c));
    return d;
}
__device__ __forceinline__ float hsum2(unsigned long long v) {
    float lo, hi;
    asm("mov.b64 {%0, %1}, %2;" : "=f"(lo), "=f"(hi) : "l"(v));
    return lo + hi;
}

// Class-split butterfly over lane bits 0-1 (3 shfl). Afterwards lane l holds
// class c = ((l&1)<<1)|((l>>1)&1) summed over its 4-lane group.
__device__ __forceinline__ float reduce_stage1(const float a[4], int lane) {
    float x = (lane & 1) ? a[0] : a[2];
    float y = (lane & 1) ? a[1] : a[3];
    float rx = __shfl_xor_sync(0xffffffffu, x, 1);
    float ry = __shfl_xor_sync(0xffffffffu, y, 1);
    float A = ((lane & 1) ? a[2] : a[0]) + rx;
    float B = ((lane & 1) ? a[3] : a[1]) + ry;
    float z = (lane & 2) ? A : B;
    float rz = __shfl_xor_sync(0xffffffffu, z, 2);
    return ((lane & 2) ? B : A) + rz;
}

// fp16 product, packed-f32x2 accumulate: 4 HMUL2 + 8 F2F + 16 FFMA2 per
// edge per lane-pair workload (was 32 scalar FFMA).
__device__ __forceinline__ void accum_edge(uint4 R, uint4 P,
                                           const unsigned long long Mp[NC][4],
                                           float a[NC]) {
    __half2 q0 = __hmul2(*reinterpret_cast<__half2*>(&R.x),
                         *reinterpret_cast<__half2*>(&P.x));
    __half2 q1 = __hmul2(*reinterpret_cast<__half2*>(&R.y),
                         *reinterpret_cast<__half2*>(&P.y));
    __half2 q2 = __hmul2(*reinterpret_cast<__half2*>(&R.z),
                         *reinterpret_cast<__half2*>(&P.z));
    __half2 q3 = __hmul2(*reinterpret_cast<__half2*>(&R.w),
                         *reinterpret_cast<__half2*>(&P.w));
    float2 f0 = __half22float2(q0);
    float2 f1 = __half22float2(q1);
    float2 f2 = __half22float2(q2);
    float2 f3 = __half22float2(q3);
    unsigned long long p0 = pack2(f0.x, f0.y);
    unsigned long long p1 = pack2(f1.x, f1.y);
    unsigned long long p2 = pack2(f2.x, f2.y);
    unsigned long long p3 = pack2(f3.x, f3.y);
#pragma unroll
    for (int j = 0; j < NC; ++j) {
        unsigned long long acc = fma2(p0, Mp[j][0], 0ull);
        acc = fma2(p1, Mp[j][1], acc);
        acc = fma2(p2, Mp[j][2], acc);
        acc = fma2(p3, Mp[j][3], acc);
        a[j] = hsum2(acc);
    }
}

// 16 lanes per edge; each halfwarp handles 4 edges per iteration (8/warp,
// all 8x16B gathers per lane issued up-front). Grid-stride loop (~2 iters)
// amortizes the folded-weight register load.
__global__ __launch_bounds__(256) void edge_kernel(
    const int* __restrict__ ridx,
    const int* __restrict__ pidx,
    float* __restrict__ out,
    int E)
{
    const int lane = threadIdx.x & 31;
    const int h    = lane & 15;
    const int sub  = lane >> 4;
    const int warp0  = (blockIdx.x * blockDim.x + threadIdx.x) >> 5;
    const int nwarps = (gridDim.x * blockDim.x) >> 5;

    // Folded-weight slice, packed for f32x2: Mp[j][k] = (M[j][8h+2k], M[j][8h+2k+1])
    const float4* Mv = reinterpret_cast<const float4*>(g_M);
    unsigned long long Mp[NC][4];
#pragma unroll
    for (int j = 0; j < NC; ++j) {
        float4 Ma = Mv[j * (DIM / 4) + 2 * h];
        float4 Mb = Mv[j * (DIM / 4) + 2 * h + 1];
        Mp[j][0] = pack2(Ma.x, Ma.y);
        Mp[j][1] = pack2(Ma.z, Ma.w);
        Mp[j][2] = pack2(Mb.x, Mb.y);
        Mp[j][3] = pack2(Mb.z, Mb.w);
    }

    const uint4* rv = reinterpret_cast<const uint4*>(g_rna);
    const uint4* pv = reinterpret_cast<const uint4*>(g_prot);

    const int ngroups = (E + EDGES_PER_WARP_ITER - 1) / EDGES_PER_WARP_ITER;
    const int c = ((h & 1) << 1) | ((h >> 1) & 1);

    for (int w = warp0; w < ngroups; w += nwarps) {
        int e[4];
        uint4 R[4], P[4];
#pragma unroll
        for (int i = 0; i < 4; ++i) {
            e[i] = 8 * w + 4 * sub + i;
            const int ec = (e[i] < E) ? e[i] : 0;
            const int ri = ridx[ec];
            const int pi = pidx[ec];
            R[i] = ldg_na(rv + (long long)ri * 16 + h);
            P[i] = ldg_na(pv + (long long)pi * 16 + h);
        }

        float a[4][NC];
#pragma unroll
        for (int i = 0; i < 4; ++i)
            accum_edge(R[i], P[i], Mp, a[i]);

#pragma unroll
        for (int i = 0; i < 4; ++i) {
            float S = reduce_stage1(a[i], lane);
            S += __shfl_xor_sync(0xffffffffu, S, 4);
            S += __shfl_xor_sync(0xffffffffu, S, 8);
            if (h < 4 && e[i] < E) out[4 * e[i] + c] = fmaxf(S, 0.f);
        }
    }
}

extern "C" void kernel_launch(void* const* d_in, const int* in_sizes, int n_in,
                              void* d_out, int out_size) {
    const float* rna  = (const float*)d_in[0];   // [20000,128] f32
    const float* prot = (const float*)d_in[1];   // [5000,128]  f32
    const int*   ridx = (const int*)d_in[2];     // [E] int32
    const int*   pidx = (const int*)d_in[3];     // [E] int32
    const float* wrel = (const float*)d_in[4];   // [4,128] f32
    const float* wcls = (const float*)d_in[5];   // [4,4]   f32
    float*       out  = (float*)d_out;           // [E,4]   f32

    const int E = in_sizes[2];
    const long long nRelem = in_sizes[0];
    const long long nPelem = in_sizes[1];

    const long long cvt_threads = (nRelem + nPelem + 7) / 8;
    const int prep_blocks = (int)((cvt_threads + 255) / 256);
    prep_kernel<<<prep_blocks, 256>>>(rna, prot, wrel, wcls, nRelem, nPelem);

    // ~TARGET_ITERS groups of 8 edges per warp; 8 warps per block.
    const long long groups = ((long long)E + EDGES_PER_WARP_ITER - 1)
                             / EDGES_PER_WARP_ITER;
    const long long warps_wanted = (groups + TARGET_ITERS - 1) / TARGET_ITERS;
    long long blocks = (warps_wanted + 7) / 8;
    if (blocks < 1) blocks = 1;
    edge_kernel<<<(int)blocks, 256>>>(ridx, pidx, out, E);
}

// round 12
// speedup vs baseline: 1.1860x; 1.1860x over previous
#include <cuda_runtime.h>
#include <cuda_fp16.h>

#define DIM   128
#define NC    4
#define NPAD  8
#define N_RNA_MAX  20000
#define N_PROT_MAX 5000

// Folded weights, fp16, padded to 8 rows: Mh[j][d] = sum_c Wc[c][j]*w_rel[c][d]
__device__ __half g_Mh[NPAD * DIM];
// fp16 copies of the gather tables (halves L2 gather flow vs fp32).
__device__ __half g_rna [N_RNA_MAX  * DIM];
__device__ __half g_prot[N_PROT_MAX * DIM];

// Prologue: fold weights into fp16 (first 1024 threads) + fp16-convert tables.
__global__ __launch_bounds__(256) void prep_kernel(
    const float* __restrict__ rna, const float* __restrict__ prot,
    const float* __restrict__ w_rel, const float* __restrict__ w_cls,
    long long nRelem, long long nPelem)
{
    const long long i = (long long)blockIdx.x * blockDim.x + threadIdx.x;

    if (i < NPAD * DIM) {
        int j = (int)(i >> 7), d = (int)(i & 127);
        float s = 0.f;
        if (j < NC) {
#pragma unroll
            for (int c = 0; c < NC; ++c)
                s += w_cls[c * NC + j] * w_rel[c * DIM + d];
        }
        g_Mh[j * DIM + d] = __float2half(s);
    }

    const long long base = i * 8;
    if (base >= nRelem + nPelem) return;
    const float* src;  __half* dst;  long long off;
    if (base < nRelem) { src = rna;  dst = g_rna;  off = base; }
    else               { src = prot; dst = g_prot; off = base - nRelem; }

    float4 f0 = *reinterpret_cast<const float4*>(src + off);
    float4 f1 = *reinterpret_cast<const float4*>(src + off + 4);
    __half2 h0 = __floats2half2_rn(f0.x, f0.y);
    __half2 h1 = __floats2half2_rn(f0.z, f0.w);
    __half2 h2 = __floats2half2_rn(f1.x, f1.y);
    __half2 h3 = __floats2half2_rn(f1.z, f1.w);
    uint4 o;
    o.x = *reinterpret_cast<unsigned*>(&h0);
    o.y = *reinterpret_cast<unsigned*>(&h1);
    o.z = *reinterpret_cast<unsigned*>(&h2);
    o.w = *reinterpret_cast<unsigned*>(&h3);
    *reinterpret_cast<uint4*>(dst + off) = o;
}

__device__ __forceinline__ unsigned s2u(const void* p) {
    unsigned r;
    asm("{ .reg .u64 t; cvta.to.shared.u64 t, %1; cvt.u32.u64 %0, t; }"
        : "=r"(r) : "l"(p));
    return r;
}

// Streaming 16B load (guaranteed-miss gathers: skip L1 allocate).
__device__ __forceinline__ uint4 ldg_na(const uint4* p) {
    uint4 v;
    asm("ld.global.L1::no_allocate.v4.u32 {%0,%1,%2,%3}, [%4];"
        : "=r"(v.x), "=r"(v.y), "=r"(v.z), "=r"(v.w) : "l"(p));
    return v;
}

// Swizzled smem byte offset for (edge_row, 16B-chunk): conflict-free for
// both the STS pattern and ldmatrix's row fetches.
__device__ __forceinline__ unsigned sw_addr(int edge, int chunk16) {
    return (unsigned)(edge * 256 + ((chunk16 ^ (edge & 7)) << 4));
}

// One warp = one 16-edge tile. Products (fp16) -> smem -> ldmatrix ->
// 8x mma.sync.m16n8k16 against folded-M fragments -> relu -> store.
__global__ __launch_bounds__(256) void edge_kernel(
    const int* __restrict__ ridx,
    const int* __restrict__ pidx,
    float* __restrict__ out,
    int E)
{
    __shared__ __align__(16) char smem[8 * 4096];   // 16 edges x 256B per warp

    const int tid  = threadIdx.x;
    const int lane = tid & 31;
    const int wid  = tid >> 5;
    const int warp_g = blockIdx.x * 8 + wid;
    const int e_base = warp_g * 16;
    const unsigned sbase = s2u(smem + wid * 4096);

    // ---- B fragments (loaded once): thread (g=lane>>2, tg=lane&3) holds
    // b0[kk] = M[g][kk*16+2tg, +1], b1[kk] = M[g][kk*16+8+2tg, +1]
    const int g  = lane >> 2;
    const int tg = lane & 3;
    const __half2* Mh2 = reinterpret_cast<const __half2*>(g_Mh);
    unsigned bf0[8], bf1[8];
#pragma unroll
    for (int kk = 0; kk < 8; ++kk) {
        __half2 x = Mh2[g * 64 + kk * 8 + tg];
        __half2 y = Mh2[g * 64 + kk * 8 + 4 + tg];
        bf0[kk] = *reinterpret_cast<unsigned*>(&x);
        bf1[kk] = *reinterpret_cast<unsigned*>(&y);
    }

    // ---- gather + product + swizzled STS: lane h owns 16B chunk h of its
    // edge; iteration it covers edges (2*it + sub). Two batches of 4 iters
    // keep 8x16B gathers in flight per lane (R9's proven MLP).
    const int h   = lane & 15;
    const int sub = lane >> 4;
    const uint4* rv = reinterpret_cast<const uint4*>(g_rna);
    const uint4* pv = reinterpret_cast<const uint4*>(g_prot);

#pragma unroll
    for (int b = 0; b < 2; ++b) {
        uint4 R[4], P[4];
        int el[4];
#pragma unroll
        for (int i = 0; i < 4; ++i) {
            const int it = b * 4 + i;
            el[i] = 2 * it + sub;
            const int e  = e_base + el[i];
            const int ec = (e < E) ? e : 0;
            R[i] = ldg_na(rv + (long long)ridx[ec] * 16 + h);
            P[i] = ldg_na(pv + (long long)pidx[ec] * 16 + h);
        }
#pragma unroll
        for (int i = 0; i < 4; ++i) {
            __half2 q0 = __hmul2(*reinterpret_cast<__half2*>(&R[i].x),
                                 *reinterpret_cast<__half2*>(&P[i].x));
            __half2 q1 = __hmul2(*reinterpret_cast<__half2*>(&R[i].y),
                                 *reinterpret_cast<__half2*>(&P[i].y));
            __half2 q2 = __hmul2(*reinterpret_cast<__half2*>(&R[i].z),
                                 *reinterpret_cast<__half2*>(&P[i].z));
            __half2 q3 = __hmul2(*reinterpret_cast<__half2*>(&R[i].w),
                                 *reinterpret_cast<__half2*>(&P[i].w));
            const unsigned addr = sbase + sw_addr(el[i], h);
            asm volatile("st.shared.v4.b32 [%0], {%1,%2,%3,%4};"
                :: "r"(addr),
                   "r"(*reinterpret_cast<unsigned*>(&q0)),
                   "r"(*reinterpret_cast<unsigned*>(&q1)),
                   "r"(*reinterpret_cast<unsigned*>(&q2)),
                   "r"(*reinterpret_cast<unsigned*>(&q3))
                : "memory");
        }
    }
    __syncwarp();

    // ---- MMA: A = products [16 edges x 128], B = M^T, D[16 x 8] fp32.
    // ldmatrix x4 matrices: m0=rows0-7/k-lo, m1=rows8-15/k-lo, m2=rows0-7/k-hi,
    // m3=rows8-15/k-hi -> exactly the m16n8k16 A fragment.
    float d0 = 0.f, d1 = 0.f, d2 = 0.f, d3 = 0.f;
    const int m    = lane >> 3;
    const int erow = ((m & 1) << 3) | (lane & 7);
#pragma unroll
    for (int kk = 0; kk < 8; ++kk) {
        const int chunk = kk * 2 + (m >> 1);
        const unsigned addr = sbase + sw_addr(erow, chunk);
        unsigned a0, a1, a2, a3;
        asm volatile("ldmatrix.sync.aligned.m8n8.x4.shared.b16 {%0,%1,%2,%3}, [%4];"
            : "=r"(a0), "=r"(a1), "=r"(a2), "=r"(a3) : "r"(addr));
        asm volatile(
            "mma.sync.aligned.m16n8k16.row.col.f32.f16.f16.f32 "
            "{%0,%1,%2,%3}, {%4,%5,%6,%7}, {%8,%9}, {%0,%1,%2,%3};"
            : "+f"(d0), "+f"(d1), "+f"(d2), "+f"(d3)
            : "r"(a0), "r"(a1), "r"(a2), "r"(a3), "r"(bf0[kk]), "r"(bf1[kk]));
    }

    // ---- epilogue: thread (g,tg), tg<2 holds cols 2tg,2tg+1 (classes) of
    // edges g and g+8.
    if (tg < 2) {
        const int e_lo = e_base + g;
        const int e_hi = e_base + g + 8;
        if (e_lo < E) {
            float2 v; v.x = fmaxf(d0, 0.f); v.y = fmaxf(d1, 0.f);
            *reinterpret_cast<float2*>(out + e_lo * 4 + 2 * tg) = v;
        }
        if (e_hi < E) {
            float2 v; v.x = fmaxf(d2, 0.f); v.y = fmaxf(d3, 0.f);
            *reinterpret_cast<float2*>(out + e_hi * 4 + 2 * tg) = v;
        }
    }
}

extern "C" void kernel_launch(void* const* d_in, const int* in_sizes, int n_in,
                              void* d_out, int out_size) {
    const float* rna  = (const float*)d_in[0];   // [20000,128] f32
    const float* prot = (const float*)d_in[1];   // [5000,128]  f32
    const int*   ridx = (const int*)d_in[2];     // [E] int32
    const int*   pidx = (const int*)d_in[3];     // [E] int32
    const float* wrel = (const float*)d_in[4];   // [4,128] f32
    const float* wcls = (const float*)d_in[5];   // [4,4]   f32
    float*       out  = (float*)d_out;           // [E,4]   f32

    const int E = in_sizes[2];
    const long long nRelem = in_sizes[0];
    const long long nPelem = in_sizes[1];

    const long long cvt_threads = (nRelem + nPelem + 7) / 8;
    const int prep_blocks = (int)((cvt_threads + 255) / 256);
    prep_kernel<<<prep_blocks, 256>>>(rna, prot, wrel, wcls, nRelem, nPelem);

    // One warp per 16 edges; 8 warps per block.
    const long long warps  = ((long long)E + 15) / 16;
    const long long blocks = (warps + 7) / 8;
    edge_kernel<<<(int)blocks, 256>>>(ridx, pidx, out, E);
}